// round 16
// baseline (speedup 1.0000x reference)
#include <cuda_runtime.h>

// TSModel 2-layer LSTM (layer0: 1->64; layer1: 64->1 fed c0; out = c1/step).
// B=2048 rows, T=1024 steps.
//
// R14 = R13 (1889us) + two-group software pipeline.
// Rows split A=0..3, B=4..6. Steady state (2 barriers/step, same as before,
// but each interval mixes FMA-burst P1, latency-chain P2, and the L1 tail):
//   alpha(t): P1(B,t) + P2(A,t) + tail(B,t-1)   | bar
//   beta(t):  P1(A,t+1) + P2(B,t) + tail(A,t)   | bar
// Deps: P1(A,t+1) reads h(A) written by P2(A,t) in alpha (bar between);
// P2(B,t) reads gbuf(B) from P1(B,t) in alpha; groups partition rows so
// single gbuf/hbuf work. Tail on warp0 (A rows) / warp1 (B rows). xtile is
// double-buffered; block k+1 staged at t%64==32.
// Everything else (decomposition, register weights, MUFU.TANH activations)
// identical to R13.

#define UNITS   64
#define TSTEPS  1024
#define ROWS    7
#define RA      4
#define RB      3
#define NCTA    296
#define NT      256
#define NROWS_TOTAL 2048

typedef unsigned long long ull;

__device__ __forceinline__ ull ffma2(ull a, ull b, ull c) {
    ull d;
    asm("fma.rn.f32x2 %0, %1, %2, %3;" : "=l"(d) : "l"(a), "l"(b), "l"(c));
    return d;
}
__device__ __forceinline__ ull pack2(float x, float y) {
    ull d;
    asm("mov.b64 %0, {%1, %2};" : "=l"(d) : "f"(x), "f"(y));
    return d;
}
__device__ __forceinline__ float2 unpack2(ull v) {
    float2 f;
    asm("mov.b64 {%0, %1}, %2;" : "=f"(f.x), "=f"(f.y) : "l"(v));
    return f;
}
__device__ __forceinline__ float tanhapx(float x) {
    float y;
    asm("tanh.approx.f32 %0, %1;" : "=f"(y) : "f"(x));
    return y;
}
__device__ __forceinline__ float sigf(float x) {
    return fmaf(0.5f, tanhapx(0.5f * x), 0.5f);
}
__device__ __forceinline__ float tanhfast(float x) {
    return tanhapx(x);
}

__global__ void __launch_bounds__(NT, 2)
lstm_kernel(const float* __restrict__ input,
            const float* __restrict__ W_ih0, const float* __restrict__ W_hh0,
            const float* __restrict__ b_ih0, const float* __restrict__ b_hh0,
            const float* __restrict__ W_ih1, const float* __restrict__ W_hh1,
            const float* __restrict__ b_ih1, const float* __restrict__ b_hh1,
            float* __restrict__ out)
{
    __shared__ __align__(16) float gbuf[ROWS][2][4][UNITS]; // K-half partials
    __shared__ __align__(16) float hbuf[ROWS][UNITS];       // h0 state
    __shared__ __align__(16) float cbuf[ROWS][68];          // c0_new (padded)
    __shared__ __align__(16) float xtile[2][ROWS][64];      // dbl-buf input
    __shared__ __align__(16) float W1s[4][68];              // W_ih1

    const int row0 = blockIdx.x * ROWS;
    if (row0 >= NROWS_TOTAL) return;    // fully-OOB CTAs exit

    const int tid  = threadIdx.x;
    const int wid  = tid >> 5;
    const int lane = tid & 31;
    const int q    = wid >> 1;          // gate type (i,f,g,o)
    const int kh   = wid & 1;           // K-half

    // ---- one-time init ----
    const int gA = 64 * q + 2 * lane;
    const int gB = gA + 1;
    ull wregA[16], wregB[16];           // weights for K-slice [32kh,32kh+32)
    {
        const ulonglong2* wa = (const ulonglong2*)(W_hh0 + gA * UNITS + 32 * kh);
        const ulonglong2* wb = (const ulonglong2*)(W_hh0 + gB * UNITS + 32 * kh);
#pragma unroll
        for (int m = 0; m < 8; m++) {
            ulonglong2 va = wa[m], vb = wb[m];
            wregA[2 * m] = va.x; wregA[2 * m + 1] = va.y;
            wregB[2 * m] = vb.x; wregB[2 * m + 1] = vb.y;
        }
    }
    const float wihA = (kh == 0) ? W_ih0[gA] : 0.0f;
    const float wihB = (kh == 0) ? W_ih0[gB] : 0.0f;
    const float bsA  = (kh == 0) ? (b_ih0[gA] + b_hh0[gA]) : 0.0f;
    const float bsB  = (kh == 0) ? (b_ih0[gB] + b_hh0[gB]) : 0.0f;

    float wh1a[4], b1a[4];
#pragma unroll
    for (int k = 0; k < 4; k++) { wh1a[k] = W_hh1[k]; b1a[k] = b_ih1[k] + b_hh1[k]; }
    if (tid < 4 * UNITS) W1s[tid >> 6][tid & 63] = W_ih1[tid];
    {
        float* hb = &hbuf[0][0];
        for (int i = tid; i < ROWS * UNITS; i += NT) hb[i] = 0.0f;
    }

    // P2 identity: unit u2; alpha handles row rs (A), beta row RA+rs (B, rs<RB)
    const int u2 = tid & 63;
    const int rs = tid >> 6;            // 0..3
    float c0s[2] = {0.f, 0.f};

    // tail identities: warp0 -> A rows (r1<RA), warp1 -> B rows (r1<RB)
    const int r1 = lane >> 2, q1 = lane & 3;
    const int rowA = (r1 < RA) ? r1 : (RA - 1);
    const int rowB = RA + ((r1 < RB) ? r1 : (RB - 1));
    const bool vgA = (r1 < RA) && (row0 + r1 < NROWS_TOTAL);
    const bool vgB = (r1 < RB) && (row0 + RA + r1 < NROWS_TOTAL);
    float h1s = 0.f, c1s = 0.f;

    __syncthreads();

#define STAGE(blk, bufi) do {                                               \
    int base_ = (blk) * 64;                                                 \
    _Pragma("unroll")                                                       \
    for (int i_ = 0; i_ < 2; i_++) {                                        \
        int lin_ = tid + NT * i_;                                           \
        if (lin_ < ROWS * 64) {                                             \
            int rr_ = lin_ >> 6, cc_ = lin_ & 63;                           \
            int grow_ = row0 + rr_;                                         \
            if (grow_ > NROWS_TOTAL - 1) grow_ = NROWS_TOTAL - 1;           \
            xtile[bufi][rr_][cc_] = input[grow_ * TSTEPS + base_ + cc_];    \
        }                                                                   \
    }                                                                       \
} while (0)

#define P1ROWS(rlo, rhi, xbuf, tmv) do {                                    \
    _Pragma("unroll")                                                       \
    for (int r_ = (rlo); r_ < (rhi); r_++) {                                \
        const ulonglong2* hv_ = (const ulonglong2*)(hbuf[r_] + 32 * kh);    \
        float xv_ = xtile[xbuf][r_][tmv];                                   \
        ull accA_ = pack2(fmaf(xv_, wihA, bsA), 0.0f);                      \
        ull accB_ = pack2(fmaf(xv_, wihB, bsB), 0.0f);                      \
        _Pragma("unroll")                                                   \
        for (int m_ = 0; m_ < 8; m_++) {                                    \
            ulonglong2 h2_ = hv_[m_];                                       \
            accA_ = ffma2(h2_.x, wregA[2 * m_],     accA_);                 \
            accB_ = ffma2(h2_.x, wregB[2 * m_],     accB_);                 \
            accA_ = ffma2(h2_.y, wregA[2 * m_ + 1], accA_);                 \
            accB_ = ffma2(h2_.y, wregB[2 * m_ + 1], accB_);                 \
        }                                                                   \
        float2 fa_ = unpack2(accA_), fb_ = unpack2(accB_);                  \
        *(ull*)&gbuf[r_][kh][q][2 * lane] =                                 \
            pack2(fa_.x + fa_.y, fb_.x + fb_.y);                            \
    }                                                                       \
} while (0)

#define P2ROW(rr_, slot) do {                                               \
    float iv_ = sigf(gbuf[rr_][0][0][u2] + gbuf[rr_][1][0][u2]);            \
    float fv_ = sigf(gbuf[rr_][0][1][u2] + gbuf[rr_][1][1][u2]);            \
    float gv_ = tanhfast(gbuf[rr_][0][2][u2] + gbuf[rr_][1][2][u2]);        \
    float ov_ = sigf(gbuf[rr_][0][3][u2] + gbuf[rr_][1][3][u2]);            \
    float c_  = fmaf(fv_, c0s[slot], iv_ * gv_);                            \
    c0s[slot] = c_;                                                         \
    hbuf[rr_][u2] = ov_ * tanhfast(c_);                                     \
    cbuf[rr_][u2] = c_;                                                     \
} while (0)

#define TAILCODE(rr_, tt_, vg_) do {                                        \
    const ulonglong2* cv_ = (const ulonglong2*)cbuf[rr_];                   \
    const ulonglong2* wv_ = (const ulonglong2*)W1s[q1];                     \
    ull pa_ = 0ULL, pb_ = 0ULL;                                             \
    _Pragma("unroll")                                                       \
    for (int m_ = 0; m_ < 16; m_++) {                                       \
        ulonglong2 c2_ = cv_[m_], w2_ = wv_[m_];                            \
        pa_ = ffma2(c2_.x, w2_.x, pa_);                                     \
        pb_ = ffma2(c2_.y, w2_.y, pb_);                                     \
    }                                                                       \
    float2 fa_ = unpack2(pa_), fb_ = unpack2(pb_);                          \
    float pre_ = (fa_.x + fb_.x) + (fa_.y + fb_.y)                          \
               + b1a[q1] + wh1a[q1] * h1s;                                  \
    float act_ = (q1 == 2) ? tanhfast(pre_) : sigf(pre_);                   \
    float a1_ = __shfl_xor_sync(0xffffffffu, act_, 1);                      \
    float gA_ = (q1 & 1) ? a1_ : act_;                                      \
    float gB_ = (q1 & 1) ? act_ : a1_;                                      \
    float cA_ = __shfl_xor_sync(0xffffffffu, gA_, 2);                       \
    float cB_ = __shfl_xor_sync(0xffffffffu, gB_, 2);                       \
    float i1_, f1_, g1_, o1_;                                               \
    if (q1 < 2) { i1_ = gA_; f1_ = gB_; g1_ = cA_; o1_ = cB_; }             \
    else        { i1_ = cA_; f1_ = cB_; g1_ = gA_; o1_ = gB_; }             \
    float c1n_ = fmaf(f1_, c1s, i1_ * g1_);                                 \
    c1s = c1n_;                                                             \
    h1s = o1_ * tanhfast(c1n_);                                             \
    if (q1 == 0 && (vg_)) out[(row0 + (rr_)) * TSTEPS + (tt_)] = c1n_;      \
} while (0)

    // ---- prologue: stage block 0, then P1(A, t=0) ----
    STAGE(0, 0);
    __syncthreads();
    P1ROWS(0, RA, 0, 0);
    __syncthreads();

    for (int t = 0; t < TSTEPS; t++) {
        const int xb = (t >> 6) & 1;
        const int tm = t & 63;

        // ---- interval alpha(t): P1(B,t) + P2(A,t) + tail(B,t-1) ----
        if (tm == 32 && t < TSTEPS - 64) STAGE((t >> 6) + 1, xb ^ 1);
        P1ROWS(RA, ROWS, xb, tm);
        P2ROW(rs, 0);
        if (wid == 1 && t > 0) TAILCODE(rowB, t - 1, vgB);
        __syncthreads();

        // ---- interval beta(t): P1(A,t+1) + P2(B,t) + tail(A,t) ----
        if (t < TSTEPS - 1) {
            const int t2 = t + 1;
            P1ROWS(0, RA, (t2 >> 6) & 1, t2 & 63);
        }
        if (rs < RB) P2ROW(RA + rs, 1);
        if (wid == 0) TAILCODE(rowA, t, vgA);
        __syncthreads();
    }
    // ---- epilogue: last B tail ----
    if (wid == 1) TAILCODE(rowB, TSTEPS - 1, vgB);

#undef STAGE
#undef P1ROWS
#undef P2ROW
#undef TAILCODE
}

extern "C" void kernel_launch(void* const* d_in, const int* in_sizes, int n_in,
                              void* d_out, int out_size) {
    const float* input = (const float*)d_in[0];
    const float* W_ih0 = (const float*)d_in[1];
    const float* W_hh0 = (const float*)d_in[2];
    const float* b_ih0 = (const float*)d_in[3];
    const float* b_hh0 = (const float*)d_in[4];
    const float* W_ih1 = (const float*)d_in[5];
    const float* W_hh1 = (const float*)d_in[6];
    const float* b_ih1 = (const float*)d_in[7];
    const float* b_hh1 = (const float*)d_in[8];
    float* out = (float*)d_out;

    lstm_kernel<<<NCTA, NT>>>(
        input, W_ih0, W_hh0, b_ih0, b_hh0, W_ih1, W_hh1, b_ih1, b_hh1, out);
}

// round 17
// speedup vs baseline: 1.1826x; 1.1826x over previous
#include <cuda_runtime.h>

// TSModel 2-layer LSTM (layer0: 1->64; layer1: 64->1 fed c0; out = c1/step).
// B=2048 rows, T=1024 steps.
//
// R16 = R13 (best: 1889us) with ONE change: P1 decomposition goes from
// (gate-type q, K-half kh) to (gate-type-PAIR gh, K-QUARTER kq).
//   Warp (gh=wid>>2, kq=wid&3): gate types {2gh, 2gh+1}, K in [16kq,16kq+16).
//   Lane l accumulates gate pairs (64t+2l, 64t+2l+1) for t=2gh,2gh+1 directly
//   in f32x2 lanes (acc.lo/hi = the two gates; h duplicated in-register).
//   h broadcast: 4 uniform LDS.128 per row = 64B (R13: 8 LDS.128 = 128B) --
//   halves the h fan-out through the crossbar, which profiling shows as the
//   co-wall (L1=68.3%). FFMA2 count unchanged (32/row). Two flat weight
//   arrays + 2 STS.64 keep codegen R13-shaped (R10's 4-array layout blew up).
// P2 combines 4 K-quarter partials per gate. Tail on warp 0, 2 barriers,
// MUFU.TANH activations, 296x256 grid: all identical to R13.

#define UNITS   64
#define TSTEPS  1024
#define ROWS    7
#define NCTA    296
#define NT      256
#define NROWS_TOTAL 2048

typedef unsigned long long ull;

__device__ __forceinline__ ull ffma2(ull a, ull b, ull c) {
    ull d;
    asm("fma.rn.f32x2 %0, %1, %2, %3;" : "=l"(d) : "l"(a), "l"(b), "l"(c));
    return d;
}
__device__ __forceinline__ ull pack2(float x, float y) {
    ull d;
    asm("mov.b64 %0, {%1, %2};" : "=l"(d) : "f"(x), "f"(y));
    return d;
}
__device__ __forceinline__ ull dup2(float x) {
    ull d;
    asm("mov.b64 %0, {%1, %1};" : "=l"(d) : "f"(x));
    return d;
}
__device__ __forceinline__ float2 unpack2(ull v) {
    float2 f;
    asm("mov.b64 {%0, %1}, %2;" : "=f"(f.x), "=f"(f.y) : "l"(v));
    return f;
}
__device__ __forceinline__ float tanhapx(float x) {
    float y;
    asm("tanh.approx.f32 %0, %1;" : "=f"(y) : "f"(x));
    return y;
}
__device__ __forceinline__ float sigf(float x) {
    return fmaf(0.5f, tanhapx(0.5f * x), 0.5f);
}
__device__ __forceinline__ float tanhfast(float x) {
    return tanhapx(x);
}

__global__ void __launch_bounds__(NT, 2)
lstm_kernel(const float* __restrict__ input,
            const float* __restrict__ W_ih0, const float* __restrict__ W_hh0,
            const float* __restrict__ b_ih0, const float* __restrict__ b_hh0,
            const float* __restrict__ W_ih1, const float* __restrict__ W_hh1,
            const float* __restrict__ b_ih1, const float* __restrict__ b_hh1,
            float* __restrict__ out)
{
    __shared__ __align__(16) float gbuf[ROWS][4][4][UNITS]; // [kq][type][unit]
    __shared__ __align__(16) float hbuf[ROWS][UNITS];       // h0 state
    __shared__ __align__(16) float cbuf[ROWS][68];          // c0_new (padded)
    __shared__ __align__(16) float xtile[ROWS][64];         // staged input
    __shared__ __align__(16) float W1s[4][68];              // W_ih1

    const int row0 = blockIdx.x * ROWS;
    if (row0 >= NROWS_TOTAL) return;    // fully-OOB CTAs exit

    const int tid  = threadIdx.x;
    const int wid  = tid >> 5;
    const int lane = tid & 31;
    const int gh   = wid >> 2;          // gate-type pair: types 2gh, 2gh+1
    const int kq   = wid & 3;           // K-quarter

    // ---- one-time init ----
    const int t0 = 2 * gh, t1 = 2 * gh + 1;
    const int gP0 = 64 * t0 + 2 * lane;   // pair (gP0, gP0+1)
    const int gP1 = 64 * t1 + 2 * lane;   // pair (gP1, gP1+1)
    // wp0[k]/wp1[k] = (W[g][16kq+k], W[g+1][16kq+k]) for the two gate pairs
    ull wp0[16], wp1[16];
#pragma unroll
    for (int k = 0; k < 16; k++) {
        int kk = 16 * kq + k;
        wp0[k] = pack2(W_hh0[gP0 * UNITS + kk], W_hh0[(gP0 + 1) * UNITS + kk]);
        wp1[k] = pack2(W_hh0[gP1 * UNITS + kk], W_hh0[(gP1 + 1) * UNITS + kk]);
    }
    // x/bias injected only by the kq==0 warps (quarters summed in P2)
    const ull wih0 = (kq == 0) ? pack2(W_ih0[gP0], W_ih0[gP0 + 1]) : 0ULL;
    const ull wih1 = (kq == 0) ? pack2(W_ih0[gP1], W_ih0[gP1 + 1]) : 0ULL;
    const ull bs0  = (kq == 0) ? pack2(b_ih0[gP0] + b_hh0[gP0],
                                       b_ih0[gP0 + 1] + b_hh0[gP0 + 1]) : 0ULL;
    const ull bs1  = (kq == 0) ? pack2(b_ih0[gP1] + b_hh0[gP1],
                                       b_ih0[gP1 + 1] + b_hh0[gP1 + 1]) : 0ULL;

    float wh1a[4], b1a[4];
#pragma unroll
    for (int k = 0; k < 4; k++) { wh1a[k] = W_hh1[k]; b1a[k] = b_ih1[k] + b_hh1[k]; }
    if (tid < 4 * UNITS) W1s[tid >> 6][tid & 63] = W_ih1[tid];
    {
        float* hb = &hbuf[0][0];
        for (int i = tid; i < ROWS * UNITS; i += NT) hb[i] = 0.0f;
    }

    // P2 identity: unit u2, rows {rs, rs+4} (second row only for rs<3)
    const int u2 = tid & 63;
    const int rs = tid >> 6;            // 0..3
    float c0s[2] = {0.f, 0.f};

    // layer-1 identity (warp 0): row r1 (0..7, clamp), gate q1
    const int r1 = tid >> 2, q1 = tid & 3;
    const int r1c = (r1 < ROWS) ? r1 : (ROWS - 1);
    float h1s = 0.f, c1s = 0.f;

    __syncthreads();

    for (int t = 0; t < TSTEPS; t++) {
        const int tm = t & 63;
        if (tm == 0) {
            // stage 64 timesteps for the CTA's rows (coalesced; clamp OOB)
#pragma unroll
            for (int i = 0; i < 2; i++) {
                int lin = tid + NT * i;
                if (lin < ROWS * 64) {
                    int rr = lin >> 6, cc = lin & 63;
                    int grow = row0 + rr;
                    if (grow > NROWS_TOTAL - 1) grow = NROWS_TOTAL - 1;
                    xtile[rr][cc] = input[grow * TSTEPS + t + cc];
                }
            }
            __syncthreads();
        }

        // ---- P1: 2 gate-pairs x 7 rows over this K-quarter ----
        //      4 uniform LDS.128 per row (64B h fan-out, half of R13)
#pragma unroll
        for (int r = 0; r < ROWS; r++) {
            const ulonglong2* hv = (const ulonglong2*)(hbuf[r] + 16 * kq);
            ull xd = dup2(xtile[r][tm]);
            ull acc0 = ffma2(xd, wih0, bs0);
            ull acc1 = ffma2(xd, wih1, bs1);
#pragma unroll
            for (int m = 0; m < 4; m++) {        // 4 x 16B = this K-quarter
                ulonglong2 h4 = hv[m];           // h[4m..4m+3] of the slice
                float2 ha = unpack2(h4.x), hb = unpack2(h4.y);
                ull d0 = dup2(ha.x), d1 = dup2(ha.y);
                ull d2 = dup2(hb.x), d3 = dup2(hb.y);
                acc0 = ffma2(d0, wp0[4 * m],     acc0);
                acc1 = ffma2(d0, wp1[4 * m],     acc1);
                acc0 = ffma2(d1, wp0[4 * m + 1], acc0);
                acc1 = ffma2(d1, wp1[4 * m + 1], acc1);
                acc0 = ffma2(d2, wp0[4 * m + 2], acc0);
                acc1 = ffma2(d2, wp1[4 * m + 2], acc1);
                acc0 = ffma2(d3, wp0[4 * m + 3], acc0);
                acc1 = ffma2(d3, wp1[4 * m + 3], acc1);
            }
            // acc0 = partial (gate gP0, gate gP0+1); acc1 likewise for t1
            *(ull*)&gbuf[r][kq][t0][2 * lane] = acc0;
            *(ull*)&gbuf[r][kq][t1][2 * lane] = acc1;
        }
        __syncthreads();   // S1: partials ready

        // ---- P2: sum 4 K-quarters + layer-0 cell update ----
#pragma unroll
        for (int j = 0; j < 2; j++) {
            const int r = rs + 4 * j;
            if (j == 1 && rs >= ROWS - 4) break;   // rows 4..6 only
            float si = (gbuf[r][0][0][u2] + gbuf[r][1][0][u2])
                     + (gbuf[r][2][0][u2] + gbuf[r][3][0][u2]);
            float sf = (gbuf[r][0][1][u2] + gbuf[r][1][1][u2])
                     + (gbuf[r][2][1][u2] + gbuf[r][3][1][u2]);
            float sg = (gbuf[r][0][2][u2] + gbuf[r][1][2][u2])
                     + (gbuf[r][2][2][u2] + gbuf[r][3][2][u2]);
            float so = (gbuf[r][0][3][u2] + gbuf[r][1][3][u2])
                     + (gbuf[r][2][3][u2] + gbuf[r][3][3][u2]);
            float iv = sigf(si), fv = sigf(sf);
            float gv = tanhfast(sg), ov = sigf(so);
            float c  = fmaf(fv, c0s[j], iv * gv);
            c0s[j] = c;
            hbuf[r][u2] = ov * tanhfast(c);
            cbuf[r][u2] = c;   // layer-1 input is the CELL state (ref quirk)
        }
        __syncthreads();   // S2: h, c0_new ready

        // ---- layer 1 (warp 0 only); other warps run ahead to next P1 ----
        if (tid < 32) {
            const ulonglong2* cv = (const ulonglong2*)cbuf[r1c];
            const ulonglong2* wv = (const ulonglong2*)W1s[q1];
            ull pa = 0ULL, pb = 0ULL;
#pragma unroll
            for (int m = 0; m < 16; m++) {       // full 64-element dot
                ulonglong2 c2 = cv[m], w2 = wv[m];
                pa = ffma2(c2.x, w2.x, pa);
                pb = ffma2(c2.y, w2.y, pb);
            }
            float2 fa = unpack2(pa), fb = unpack2(pb);
            float pre = (fa.x + fb.x) + (fa.y + fb.y)
                      + b1a[q1] + wh1a[q1] * h1s;
            float act = (q1 == 2) ? tanhfast(pre) : sigf(pre);

            // gather the 4 gate values within each 4-lane row group
            float a1 = __shfl_xor_sync(0xffffffffu, act, 1);
            float gAv = (q1 & 1) ? a1 : act;    // gate[q & ~1]
            float gBv = (q1 & 1) ? act : a1;    // gate[q | 1]
            float cA = __shfl_xor_sync(0xffffffffu, gAv, 2);
            float cB = __shfl_xor_sync(0xffffffffu, gBv, 2);
            float i1, f1, g1v, o1v;
            if (q1 < 2) { i1 = gAv; f1 = gBv; g1v = cA; o1v = cB; }
            else        { i1 = cA;  f1 = cB;  g1v = gAv; o1v = gBv; }

            float c1n = fmaf(f1, c1s, i1 * g1v);
            c1s = c1n;
            h1s = o1v * tanhfast(c1n);
            if (q1 == 0 && r1 < ROWS && (row0 + r1) < NROWS_TOTAL)
                out[(row0 + r1) * TSTEPS + t] = c1n;
        }
    }
}

extern "C" void kernel_launch(void* const* d_in, const int* in_sizes, int n_in,
                              void* d_out, int out_size) {
    const float* input = (const float*)d_in[0];
    const float* W_ih0 = (const float*)d_in[1];
    const float* W_hh0 = (const float*)d_in[2];
    const float* b_ih0 = (const float*)d_in[3];
    const float* b_hh0 = (const float*)d_in[4];
    const float* W_ih1 = (const float*)d_in[5];
    const float* W_hh1 = (const float*)d_in[6];
    const float* b_ih1 = (const float*)d_in[7];
    const float* b_hh1 = (const float*)d_in[8];
    float* out = (float*)d_out;

    lstm_kernel<<<NCTA, NT>>>(
        input, W_ih0, W_hh0, b_ih0, b_hh0, W_ih1, W_hh1, b_ih1, b_hh1, out);
}